// round 1
// baseline (speedup 1.0000x reference)
#include <cuda_runtime.h>
#include <cstdint>

#define N_NODES 300000
#define N_EDGES 600000
#define N_GRAPHS 12000
#define HID 128
#define F_ATOM 9
#define V_ATOM 119
#define D_ATOM 9

// ---------------- scratch (device globals; no allocations allowed) ----------
__device__ float g_h1[(size_t)N_NODES * HID];    // h1, later reused as agg2
__device__ float g_agg1[(size_t)N_NODES * HID];  // agg1 (= Â h1 + b1)
__device__ float g_deg[N_NODES];
__device__ float g_dinv[N_NODES];
__device__ float g_cnt[N_GRAPHS];
__device__ float g_pool[N_GRAPHS * HID];
__device__ float g_wc[HID * HID];
__device__ float g_bc[HID];

// ---------------- init: deg=1, cnt=0, pool=0 --------------------------------
__global__ void k_init() {
    int i = blockIdx.x * blockDim.x + threadIdx.x;
    int stride = gridDim.x * blockDim.x;
    for (int j = i; j < N_GRAPHS * HID; j += stride) g_pool[j] = 0.f;
    for (int j = i; j < N_GRAPHS; j += stride) g_cnt[j] = 0.f;
    for (int j = i; j < N_NODES; j += stride) g_deg[j] = 1.f;
}

// ---------------- degree + per-graph node counts ----------------------------
__global__ void k_count(const int* __restrict__ ei, const int* __restrict__ batch) {
    int i = blockIdx.x * blockDim.x + threadIdx.x;
    int stride = gridDim.x * blockDim.x;
    for (int e = i; e < N_EDGES; e += stride) {
        int dst = ei[N_EDGES + e];
        atomicAdd(&g_deg[dst], 1.f);
    }
    for (int n = i; n < N_NODES; n += stride) {
        atomicAdd(&g_cnt[batch[n]], 1.f);
    }
}

__global__ void k_dinv() {
    int n = blockIdx.x * blockDim.x + threadIdx.x;
    if (n < N_NODES) g_dinv[n] = rsqrtf(g_deg[n]);
}

// ---------------- embed + h1 = h0@W1 ; agg1 self-term init ------------------
// blockDim 256 = 8 warps, one node per warp.
__global__ void k_embed(const int* __restrict__ x, const float* __restrict__ emb,
                        const float* __restrict__ W1, const float* __restrict__ b1) {
    __shared__ float W1s[F_ATOM * HID];
    __shared__ float b1s[HID];
    int tid = threadIdx.x;
    for (int i = tid; i < F_ATOM * HID; i += 256) W1s[i] = W1[i];
    if (tid < HID) b1s[tid] = b1[tid];
    __syncthreads();

    int warp = tid >> 5, lane = tid & 31;
    int n = blockIdx.x * 8 + warp;
    if (n >= N_NODES) return;

    int xv = 0;
    if (lane < F_ATOM) xv = x[n * F_ATOM + lane];
    int xf[F_ATOM];
#pragma unroll
    for (int f = 0; f < F_ATOM; f++) xf[f] = __shfl_sync(0xffffffffu, xv, f);

    float h0v = 0.f;
    if (lane < D_ATOM) {
#pragma unroll
        for (int f = 0; f < F_ATOM; f++)
            h0v += emb[(f * V_ATOM + xf[f]) * D_ATOM + lane];
    }
    float h0[D_ATOM];
#pragma unroll
    for (int d = 0; d < D_ATOM; d++) h0[d] = __shfl_sync(0xffffffffu, h0v, d);

    float dv = g_dinv[n];
    float dv2 = dv * dv;
    size_t base = (size_t)n * HID;
#pragma unroll
    for (int j = 0; j < 4; j++) {
        int c = j * 32 + lane;
        float acc = 0.f;
#pragma unroll
        for (int d = 0; d < D_ATOM; d++) acc += h0[d] * W1s[d * HID + c];
        g_h1[base + c] = acc;
        g_agg1[base + c] = acc * dv2 + b1s[c];
    }
}

// ---------------- edge aggregation: warp per edge, red.v4.f32 ---------------
// SECOND=false: agg1 += h1[src]*coef          (read g_h1,   write g_agg1)
// SECOND=true : agg2 += relu(agg1[src])*coef  (read g_agg1, write g_h1)
template <bool SECOND>
__global__ void k_edge(const int* __restrict__ ei) {
    int e = blockIdx.x * 8 + (threadIdx.x >> 5);
    if (e >= N_EDGES) return;
    int lane = threadIdx.x & 31;
    int src = ei[e];
    int dst = ei[N_EDGES + e];
    float c = g_dinv[src] * g_dinv[dst];

    const float4* sp = (const float4*)((SECOND ? g_agg1 : g_h1) + (size_t)src * HID);
    float4 v = sp[lane];
    if (SECOND) {
        v.x = fmaxf(v.x, 0.f); v.y = fmaxf(v.y, 0.f);
        v.z = fmaxf(v.z, 0.f); v.w = fmaxf(v.w, 0.f);
    }
    float* ap = (SECOND ? g_h1 : g_agg1) + (size_t)dst * HID + lane * 4;
    asm volatile("red.global.add.v4.f32 [%0], {%1,%2,%3,%4};"
                 :: "l"(ap), "f"(v.x * c), "f"(v.y * c), "f"(v.z * c), "f"(v.w * c)
                 : "memory");
}

// ---------------- agg2 self-term init: h1buf = relu(agg1)*dinv^2 ------------
__global__ void k_agg2init() {
    int i = blockIdx.x * blockDim.x + threadIdx.x;           // float4 index
    const int TOT = N_NODES * (HID / 4);
    if (i >= TOT) return;
    int n = i >> 5;                                           // 32 float4 per row
    float dv = g_dinv[n];
    float s = dv * dv;
    float4 v = ((const float4*)g_agg1)[i];
    v.x = fmaxf(v.x, 0.f) * s; v.y = fmaxf(v.y, 0.f) * s;
    v.z = fmaxf(v.z, 0.f) * s; v.w = fmaxf(v.w, 0.f) * s;
    ((float4*)g_h1)[i] = v;
}

// ---------------- pooling: run-length compressed atomics (batch sorted) -----
// blockDim 128 (one channel per thread), 32 consecutive nodes per block.
__global__ void k_pool(const int* __restrict__ batch) {
    __shared__ int bsh[32];
    int base = blockIdx.x * 32;
    int c = threadIdx.x;
    if (c < 32) bsh[c] = batch[base + c];   // N_NODES % 32 == 0
    __syncthreads();

    int cur = bsh[0];
    float acc = 0.f;
#pragma unroll 4
    for (int i = 0; i < 32; i++) {
        int b = bsh[i];
        if (b != cur) {
            atomicAdd(&g_pool[cur * HID + c], acc);
            cur = b; acc = 0.f;
        }
        acc += g_h1[(size_t)(base + i) * HID + c];
    }
    atomicAdd(&g_pool[cur * HID + c], acc);
}

// ---------------- Wc = W2 @ Wfc ; Bc = b2 @ Wfc + bfc -----------------------
__global__ void k_wc(const float* __restrict__ W2, const float* __restrict__ Wfc,
                     const float* __restrict__ b2, const float* __restrict__ bfc) {
    int i = blockIdx.x;     // row of W2
    int j = threadIdx.x;    // col of Wfc
    float acc = 0.f;
    for (int k = 0; k < HID; k++) acc += W2[i * HID + k] * Wfc[k * HID + j];
    g_wc[i * HID + j] = acc;
    if (i == 0) {
        float a = bfc[j];
        for (int k = 0; k < HID; k++) a += b2[k] * Wfc[k * HID + j];
        g_bc[j] = a;
    }
}

// ---------------- final: out = (pool/cnt) @ Wc + Bc -------------------------
__global__ void k_out(float* __restrict__ out) {
    __shared__ float p[HID];
    int g = blockIdx.x;
    int c = threadIdx.x;
    float cnt = fmaxf(g_cnt[g], 1.f);
    p[c] = g_pool[g * HID + c] / cnt;
    __syncthreads();
    float acc = g_bc[c];
#pragma unroll 8
    for (int k = 0; k < HID; k++) acc += p[k] * g_wc[k * HID + c];
    out[g * HID + c] = acc;
}

// ---------------- launch ----------------------------------------------------
extern "C" void kernel_launch(void* const* d_in, const int* in_sizes, int n_in,
                              void* d_out, int out_size) {
    const int*   x     = (const int*)d_in[0];
    const int*   ei    = (const int*)d_in[1];
    // d_in[2] = edge_attr (unused: bond embedding is dead code in reference)
    const int*   batch = (const int*)d_in[3];
    const float* aemb  = (const float*)d_in[4];
    // d_in[5] = bond_emb (unused)
    const float* W1    = (const float*)d_in[6];
    const float* b1    = (const float*)d_in[7];
    const float* W2    = (const float*)d_in[8];
    const float* b2    = (const float*)d_in[9];
    const float* Wfc   = (const float*)d_in[10];
    const float* bfc   = (const float*)d_in[11];
    float* out = (float*)d_out;

    k_init<<<6000, 256>>>();
    k_count<<<(N_EDGES + 255) / 256, 256>>>(ei, batch);
    k_dinv<<<(N_NODES + 255) / 256, 256>>>();
    k_embed<<<(N_NODES + 7) / 8, 256>>>(x, aemb, W1, b1);
    k_edge<false><<<(N_EDGES + 7) / 8, 256>>>(ei);
    k_agg2init<<<(N_NODES * (HID / 4) + 255) / 256, 256>>>();
    k_edge<true><<<(N_EDGES + 7) / 8, 256>>>(ei);
    k_pool<<<N_NODES / 32, 128>>>(batch);
    k_wc<<<HID, HID>>>(W2, Wfc, b2, bfc);
    k_out<<<N_GRAPHS, HID>>>(out);
}

// round 2
// speedup vs baseline: 1.5792x; 1.5792x over previous
#include <cuda_runtime.h>
#include <cuda_fp16.h>
#include <cstdint>

#define N_NODES 300000
#define N_EDGES 600000
#define N_GRAPHS 12000
#define HID 128
#define F_ATOM 9
#define V_ATOM 119
#define D_ATOM 9
#define EMB_SZ (F_ATOM * V_ATOM * D_ATOM)   // 9639 floats = 38556 B

#define SCAN_E 1024
#define NSB ((N_NODES + SCAN_E - 1) / SCAN_E)   // 293

// ---------------- scratch (device globals; no allocations allowed) ----------
__device__ __half g_h1h[(size_t)N_NODES * HID];   // h1 (fp16); reused as agg2 after pass1
__device__ __half g_a1h[(size_t)N_NODES * HID];   // agg1 (fp16)
__device__ int    g_deg[N_NODES];                 // incoming degree (excl self)
__device__ float  g_dinv[N_NODES];
__device__ int    g_rowptr[N_NODES + 1];
__device__ int    g_fill[N_NODES];
__device__ int    g_csrsrc[N_EDGES];
__device__ int    g_bsum[NSB];
__device__ float  g_cnt[N_GRAPHS];
__device__ float  g_pool[N_GRAPHS * HID];
__device__ float  g_wc[HID * HID];
__device__ float  g_bc[HID];

// ---------------- init: deg=0, cnt=0, pool=0 --------------------------------
__global__ void k_init() {
    int i = blockIdx.x * blockDim.x + threadIdx.x;
    int stride = gridDim.x * blockDim.x;
    for (int j = i; j < N_GRAPHS * HID; j += stride) g_pool[j] = 0.f;
    for (int j = i; j < N_GRAPHS; j += stride) g_cnt[j] = 0.f;
    for (int j = i; j < N_NODES; j += stride) g_deg[j] = 0;
}

// ---------------- degree + per-graph node counts ----------------------------
__global__ void k_deg(const int* __restrict__ ei, const int* __restrict__ batch) {
    int i = blockIdx.x * blockDim.x + threadIdx.x;
    int stride = gridDim.x * blockDim.x;
    for (int e = i; e < N_EDGES; e += stride)
        atomicAdd(&g_deg[ei[N_EDGES + e]], 1);
    for (int n = i; n < N_NODES; n += stride)
        atomicAdd(&g_cnt[batch[n]], 1.f);
}

// ---------------- 3-kernel exclusive scan of deg -> rowptr ------------------
__global__ void k_scan1() {
    __shared__ int s[256];
    int t = threadIdx.x;
    int base = blockIdx.x * SCAN_E + t * 4;
    int v[4];
#pragma unroll
    for (int k = 0; k < 4; k++) v[k] = (base + k < N_NODES) ? g_deg[base + k] : 0;
    v[1] += v[0]; v[2] += v[1]; v[3] += v[2];
    s[t] = v[3];
    __syncthreads();
    for (int off = 1; off < 256; off <<= 1) {
        int add = (t >= off) ? s[t - off] : 0;
        __syncthreads();
        s[t] += add;
        __syncthreads();
    }
    int pre = (t > 0) ? s[t - 1] : 0;
#pragma unroll
    for (int k = 0; k < 4; k++)
        if (base + k < N_NODES) g_rowptr[base + k + 1] = v[k] + pre;
    if (t == 255) g_bsum[blockIdx.x] = s[255];
}

__global__ void k_scan2() {
    __shared__ int s[512];
    int t = threadIdx.x;
    s[t] = (t < NSB) ? g_bsum[t] : 0;
    __syncthreads();
    for (int off = 1; off < 512; off <<= 1) {
        int add = (t >= off) ? s[t - off] : 0;
        __syncthreads();
        s[t] += add;
        __syncthreads();
    }
    if (t < NSB) g_bsum[t] = s[t];
}

__global__ void k_scan3() {
    int i = blockIdx.x * blockDim.x + threadIdx.x;
    if (i >= N_NODES) return;
    int blk = i / SCAN_E;
    int add = (blk > 0) ? g_bsum[blk - 1] : 0;
    int incl = g_rowptr[i + 1] + add;
    g_rowptr[i + 1] = incl;
    g_fill[i] = incl - g_deg[i];                 // exclusive start
    g_dinv[i] = rsqrtf((float)g_deg[i] + 1.0f);  // deg incl self-loop
    if (i == 0) g_rowptr[0] = 0;
}

// ---------------- scatter edges into CSR ------------------------------------
__global__ void k_scatter(const int* __restrict__ ei) {
    int e = blockIdx.x * blockDim.x + threadIdx.x;
    if (e >= N_EDGES) return;
    int src = ei[e];
    int dst = ei[N_EDGES + e];
    int pos = atomicAdd(&g_fill[dst], 1);
    g_csrsrc[pos] = src;
}

// ---------------- embed + h1 = h0@W1 (fp16 out) ------------------------------
// Persistent-ish blocks: emb table in smem, W1 columns in registers.
__global__ void __launch_bounds__(256) k_embed(const int* __restrict__ x,
                                               const float* __restrict__ emb,
                                               const float* __restrict__ W1) {
    __shared__ float s_emb[EMB_SZ];
    __shared__ float s_h0[8][16];
    int tid = threadIdx.x;
    for (int i = tid; i < EMB_SZ; i += 256) s_emb[i] = emb[i];

    int warp = tid >> 5, lane = tid & 31;
    // W1 columns for this lane: w[d] = W1[d][4*lane .. 4*lane+3]
    float4 w[D_ATOM];
    const float4* W1v = (const float4*)W1;
#pragma unroll
    for (int d = 0; d < D_ATOM; d++) w[d] = W1v[d * (HID / 4) + lane];
    __syncthreads();

    int gwarp = blockIdx.x * 8 + warp;
    const int NW = 592 * 8;
    for (int n = gwarp; n < N_NODES; n += NW) {
        int xv = 0;
        if (lane < F_ATOM) xv = x[n * F_ATOM + lane];
        int xf[F_ATOM];
#pragma unroll
        for (int f = 0; f < F_ATOM; f++) xf[f] = __shfl_sync(0xffffffffu, xv, f);

        if (lane < D_ATOM) {
            float h = 0.f;
#pragma unroll
            for (int f = 0; f < F_ATOM; f++)
                h += s_emb[(f * V_ATOM + xf[f]) * D_ATOM + lane];
            s_h0[warp][lane] = h;
        }
        __syncwarp();
        float4 acc = make_float4(0.f, 0.f, 0.f, 0.f);
#pragma unroll
        for (int d = 0; d < D_ATOM; d++) {
            float h = s_h0[warp][d];
            acc.x += h * w[d].x; acc.y += h * w[d].y;
            acc.z += h * w[d].z; acc.w += h * w[d].w;
        }
        __syncwarp();

        __half2 p0 = __floats2half2_rn(acc.x, acc.y);
        __half2 p1 = __floats2half2_rn(acc.z, acc.w);
        uint2 u;
        u.x = *reinterpret_cast<unsigned*>(&p0);
        u.y = *reinterpret_cast<unsigned*>(&p1);
        ((uint2*)(g_h1h + (size_t)n * HID))[lane] = u;
    }
}

// ---------------- CSR aggregation passes -------------------------------------
// pass1: agg1 = sum_{src->n} h1[src]*dinv[s]*dinv[n] + h1[n]*dinv[n]^2 + b1
// pass2: agg2 = sum relu(agg1[src])*coef + relu(agg1[n])*dinv[n]^2   (-> g_h1h)
__device__ __forceinline__ float4 unpack_h4(uint2 u) {
    __half2 a = *reinterpret_cast<__half2*>(&u.x);
    __half2 b = *reinterpret_cast<__half2*>(&u.y);
    float2 fa = __half22float2(a), fb = __half22float2(b);
    return make_float4(fa.x, fa.y, fb.x, fb.y);
}

template <bool SECOND>
__global__ void __launch_bounds__(256) k_pass(const float* __restrict__ b1) {
    int n = blockIdx.x * 8 + (threadIdx.x >> 5);
    if (n >= N_NODES) return;
    int lane = threadIdx.x & 31;

    int r0 = g_rowptr[n];
    int r1 = g_rowptr[n + 1];
    float dn = g_dinv[n];
    const __half* IN = SECOND ? g_a1h : g_h1h;

    // self term
    uint2 u = ((const uint2*)(IN + (size_t)n * HID))[lane];
    float4 v = unpack_h4(u);
    if (SECOND) {
        v.x = fmaxf(v.x, 0.f); v.y = fmaxf(v.y, 0.f);
        v.z = fmaxf(v.z, 0.f); v.w = fmaxf(v.w, 0.f);
    }
    float s = dn * dn;
    float4 acc = make_float4(v.x * s, v.y * s, v.z * s, v.w * s);
    if (!SECOND) {
        float4 bb = ((const float4*)b1)[lane];
        acc.x += bb.x; acc.y += bb.y; acc.z += bb.z; acc.w += bb.w;
    }

    for (int j = r0; j < r1; j++) {
        int src = g_csrsrc[j];
        float c = g_dinv[src] * dn;
        uint2 us = ((const uint2*)(IN + (size_t)src * HID))[lane];
        float4 vs = unpack_h4(us);
        if (SECOND) {
            vs.x = fmaxf(vs.x, 0.f); vs.y = fmaxf(vs.y, 0.f);
            vs.z = fmaxf(vs.z, 0.f); vs.w = fmaxf(vs.w, 0.f);
        }
        acc.x += vs.x * c; acc.y += vs.y * c;
        acc.z += vs.z * c; acc.w += vs.w * c;
    }

    __half* OUT = SECOND ? g_h1h : g_a1h;   // pass2 reuses h1 buffer for agg2
    __half2 p0 = __floats2half2_rn(acc.x, acc.y);
    __half2 p1 = __floats2half2_rn(acc.z, acc.w);
    uint2 uo;
    uo.x = *reinterpret_cast<unsigned*>(&p0);
    uo.y = *reinterpret_cast<unsigned*>(&p1);
    ((uint2*)(OUT + (size_t)n * HID))[lane] = uo;
}

// ---------------- pooling: run-length compressed atomics (batch sorted) -----
__global__ void k_pool(const int* __restrict__ batch) {
    __shared__ int bsh[32];
    int base = blockIdx.x * 32;
    int c = threadIdx.x;
    if (c < 32) bsh[c] = batch[base + c];   // N_NODES % 32 == 0
    __syncthreads();

    int cur = bsh[0];
    float acc = 0.f;
#pragma unroll 4
    for (int i = 0; i < 32; i++) {
        int b = bsh[i];
        if (b != cur) {
            atomicAdd(&g_pool[cur * HID + c], acc);
            cur = b; acc = 0.f;
        }
        acc += __half2float(g_h1h[(size_t)(base + i) * HID + c]);
    }
    atomicAdd(&g_pool[cur * HID + c], acc);
}

// ---------------- Wc = W2 @ Wfc ; Bc = b2 @ Wfc + bfc -----------------------
__global__ void k_wc(const float* __restrict__ W2, const float* __restrict__ Wfc,
                     const float* __restrict__ b2, const float* __restrict__ bfc) {
    int i = blockIdx.x;
    int j = threadIdx.x;
    float acc = 0.f;
    for (int k = 0; k < HID; k++) acc += W2[i * HID + k] * Wfc[k * HID + j];
    g_wc[i * HID + j] = acc;
    if (i == 0) {
        float a = bfc[j];
        for (int k = 0; k < HID; k++) a += b2[k] * Wfc[k * HID + j];
        g_bc[j] = a;
    }
}

// ---------------- final: out = (pool/cnt) @ Wc + Bc -------------------------
__global__ void k_out(float* __restrict__ out) {
    __shared__ float p[HID];
    int g = blockIdx.x;
    int c = threadIdx.x;
    float cnt = fmaxf(g_cnt[g], 1.f);
    p[c] = g_pool[g * HID + c] / cnt;
    __syncthreads();
    float acc = g_bc[c];
#pragma unroll 8
    for (int k = 0; k < HID; k++) acc += p[k] * g_wc[k * HID + c];
    out[g * HID + c] = acc;
}

// ---------------- launch ----------------------------------------------------
extern "C" void kernel_launch(void* const* d_in, const int* in_sizes, int n_in,
                              void* d_out, int out_size) {
    const int*   x     = (const int*)d_in[0];
    const int*   ei    = (const int*)d_in[1];
    const int*   batch = (const int*)d_in[3];
    const float* aemb  = (const float*)d_in[4];
    const float* W1    = (const float*)d_in[6];
    const float* b1    = (const float*)d_in[7];
    const float* W2    = (const float*)d_in[8];
    const float* b2    = (const float*)d_in[9];
    const float* Wfc   = (const float*)d_in[10];
    const float* bfc   = (const float*)d_in[11];
    float* out = (float*)d_out;

    k_init<<<2048, 256>>>();
    k_deg<<<2048, 256>>>(ei, batch);
    k_scan1<<<NSB, 256>>>();
    k_scan2<<<1, 512>>>();
    k_scan3<<<(N_NODES + 255) / 256, 256>>>();
    k_scatter<<<(N_EDGES + 255) / 256, 256>>>(ei);
    k_embed<<<592, 256>>>(x, aemb, W1);
    k_pass<false><<<(N_NODES + 7) / 8, 256>>>(b1);
    k_pass<true><<<(N_NODES + 7) / 8, 256>>>(b1);
    k_pool<<<N_NODES / 32, 128>>>(batch);
    k_wc<<<HID, HID>>>(W2, Wfc, b2, bfc);
    k_out<<<N_GRAPHS, HID>>>(out);
}

// round 4
// speedup vs baseline: 1.9294x; 1.2218x over previous
#include <cuda_runtime.h>
#include <cuda_fp16.h>
#include <cstdint>

#define N_NODES 300000
#define N_EDGES 600000
#define N_GRAPHS 12000
#define HID 128
#define F_ATOM 9
#define V_ATOM 119
#define D_ATOM 9
#define EMB_SZ (F_ATOM * V_ATOM * D_ATOM)   // 9639 floats = 38556 B

#define SCAN_E 1024
#define NSB ((N_NODES + SCAN_E - 1) / SCAN_E)   // 293

// ---------------- scratch (device globals; no allocations allowed) ----------
__device__ __half g_h1h[(size_t)N_NODES * HID];   // h1 (fp16)
__device__ __half g_a1h[(size_t)N_NODES * HID];   // relu(agg1) (fp16)
__device__ int    g_deg[N_NODES];
__device__ float  g_dinv[N_NODES];
__device__ int    g_rowptr[N_NODES + 1];
__device__ int    g_fill[N_NODES];
__device__ int    g_csrsrc[N_EDGES];
__device__ int    g_bsum[NSB];
__device__ float  g_cnt[N_GRAPHS];
__device__ float  g_pool[N_GRAPHS * HID];
__device__ float  g_wc[HID * HID];
__device__ float  g_bc[HID];

// ---------------- init: deg=0, cnt=0, pool=0 --------------------------------
__global__ void k_init() {
    int i = blockIdx.x * blockDim.x + threadIdx.x;
    int stride = gridDim.x * blockDim.x;
    for (int j = i; j < N_GRAPHS * HID; j += stride) g_pool[j] = 0.f;
    for (int j = i; j < N_GRAPHS; j += stride) g_cnt[j] = 0.f;
    for (int j = i; j < N_NODES; j += stride) g_deg[j] = 0;
}

// ---------------- degree + per-graph node counts ----------------------------
__global__ void k_deg(const int* __restrict__ ei, const int* __restrict__ batch) {
    int i = blockIdx.x * blockDim.x + threadIdx.x;
    int stride = gridDim.x * blockDim.x;
    for (int e = i; e < N_EDGES; e += stride)
        atomicAdd(&g_deg[ei[N_EDGES + e]], 1);
    for (int n = i; n < N_NODES; n += stride)
        atomicAdd(&g_cnt[batch[n]], 1.f);
}

// ---------------- 3-kernel exclusive scan of deg -> rowptr ------------------
__global__ void k_scan1() {
    __shared__ int s[256];
    int t = threadIdx.x;
    int base = blockIdx.x * SCAN_E + t * 4;
    int v[4];
#pragma unroll
    for (int k = 0; k < 4; k++) v[k] = (base + k < N_NODES) ? g_deg[base + k] : 0;
    v[1] += v[0]; v[2] += v[1]; v[3] += v[2];
    s[t] = v[3];
    __syncthreads();
    for (int off = 1; off < 256; off <<= 1) {
        int add = (t >= off) ? s[t - off] : 0;
        __syncthreads();
        s[t] += add;
        __syncthreads();
    }
    int pre = (t > 0) ? s[t - 1] : 0;
#pragma unroll
    for (int k = 0; k < 4; k++)
        if (base + k < N_NODES) g_rowptr[base + k + 1] = v[k] + pre;
    if (t == 255) g_bsum[blockIdx.x] = s[255];
}

__global__ void k_scan2() {
    __shared__ int s[512];
    int t = threadIdx.x;
    s[t] = (t < NSB) ? g_bsum[t] : 0;
    __syncthreads();
    for (int off = 1; off < 512; off <<= 1) {
        int add = (t >= off) ? s[t - off] : 0;
        __syncthreads();
        s[t] += add;
        __syncthreads();
    }
    if (t < NSB) g_bsum[t] = s[t];
}

__global__ void k_scan3() {
    int i = blockIdx.x * blockDim.x + threadIdx.x;
    if (i >= N_NODES) return;
    int blk = i / SCAN_E;
    int add = (blk > 0) ? g_bsum[blk - 1] : 0;
    int incl = g_rowptr[i + 1] + add;
    g_rowptr[i + 1] = incl;
    g_fill[i] = incl - g_deg[i];                 // exclusive start
    g_dinv[i] = rsqrtf((float)g_deg[i] + 1.0f);  // deg incl self-loop
    if (i == 0) g_rowptr[0] = 0;
}

// ---------------- scatter edges into CSR ------------------------------------
__global__ void k_scatter(const int* __restrict__ ei) {
    int e = blockIdx.x * blockDim.x + threadIdx.x;
    if (e >= N_EDGES) return;
    int src = ei[e];
    int dst = ei[N_EDGES + e];
    int pos = atomicAdd(&g_fill[dst], 1);
    g_csrsrc[pos] = src;
}

// ---------------- embed + h1 = h0@W1 (fp16 out) ------------------------------
__global__ void __launch_bounds__(256) k_embed(const int* __restrict__ x,
                                               const float* __restrict__ emb,
                                               const float* __restrict__ W1) {
    __shared__ float s_emb[EMB_SZ];
    __shared__ float s_h0[8][16];
    int tid = threadIdx.x;
    for (int i = tid; i < EMB_SZ; i += 256) s_emb[i] = emb[i];

    int warp = tid >> 5, lane = tid & 31;
    float4 w[D_ATOM];
    const float4* W1v = (const float4*)W1;
#pragma unroll
    for (int d = 0; d < D_ATOM; d++) w[d] = W1v[d * (HID / 4) + lane];
    __syncthreads();

    int gwarp = blockIdx.x * 8 + warp;
    const int NW = 592 * 8;
    for (int n = gwarp; n < N_NODES; n += NW) {
        int xv = 0;
        if (lane < F_ATOM) xv = __ldg(&x[n * F_ATOM + lane]);
        int xf[F_ATOM];
#pragma unroll
        for (int f = 0; f < F_ATOM; f++) xf[f] = __shfl_sync(0xffffffffu, xv, f);

        if (lane < D_ATOM) {
            float h = 0.f;
#pragma unroll
            for (int f = 0; f < F_ATOM; f++)
                h += s_emb[(f * V_ATOM + xf[f]) * D_ATOM + lane];
            s_h0[warp][lane] = h;
        }
        __syncwarp();
        float4 acc = make_float4(0.f, 0.f, 0.f, 0.f);
#pragma unroll
        for (int d = 0; d < D_ATOM; d++) {
            float h = s_h0[warp][d];
            acc.x += h * w[d].x; acc.y += h * w[d].y;
            acc.z += h * w[d].z; acc.w += h * w[d].w;
        }
        __syncwarp();

        __half2 p0 = __floats2half2_rn(acc.x, acc.y);
        __half2 p1 = __floats2half2_rn(acc.z, acc.w);
        uint2 u;
        u.x = *reinterpret_cast<unsigned*>(&p0);
        u.y = *reinterpret_cast<unsigned*>(&p1);
        ((uint2*)(g_h1h + (size_t)n * HID))[lane] = u;
    }
}

// ---------------- helpers ----------------------------------------------------
__device__ __forceinline__ float4 unpack_h4(uint2 u) {
    __half2 a = *reinterpret_cast<__half2*>(&u.x);
    __half2 b = *reinterpret_cast<__half2*>(&u.y);
    float2 fa = __half22float2(a), fb = __half22float2(b);
    return make_float4(fa.x, fa.y, fb.x, fb.y);
}

// ---------------- pass1: relu(agg1) = relu(Â h1 + b1) -> g_a1h ---------------
__global__ void __launch_bounds__(256) k_pass1(const float* __restrict__ b1) {
    int n = blockIdx.x * 8 + (threadIdx.x >> 5);
    if (n >= N_NODES) return;
    int lane = threadIdx.x & 31;

    int r0 = __ldg(&g_rowptr[n]);
    int r1 = __ldg(&g_rowptr[n + 1]);
    float dn = __ldg(&g_dinv[n]);

    // self term + bias
    uint2 u = __ldg(((const uint2*)(g_h1h + (size_t)n * HID)) + lane);
    float4 v = unpack_h4(u);
    float s = dn * dn;
    float4 bb = __ldg(((const float4*)b1) + lane);
    float4 acc = make_float4(v.x * s + bb.x, v.y * s + bb.y,
                             v.z * s + bb.z, v.w * s + bb.w);

    // pipelined gather loop
    int src_next = (r0 < r1) ? __ldg(&g_csrsrc[r0]) : 0;
    for (int j = r0; j < r1; j++) {
        int src = src_next;
        if (j + 1 < r1) src_next = __ldg(&g_csrsrc[j + 1]);
        float c = __ldg(&g_dinv[src]) * dn;
        uint2 us = __ldg(((const uint2*)(g_h1h + (size_t)src * HID)) + lane);
        float4 vs = unpack_h4(us);
        acc.x += vs.x * c; acc.y += vs.y * c;
        acc.z += vs.z * c; acc.w += vs.w * c;
    }

    // store with relu applied (downstream only uses relu(agg1))
    acc.x = fmaxf(acc.x, 0.f); acc.y = fmaxf(acc.y, 0.f);
    acc.z = fmaxf(acc.z, 0.f); acc.w = fmaxf(acc.w, 0.f);
    __half2 p0 = __floats2half2_rn(acc.x, acc.y);
    __half2 p1 = __floats2half2_rn(acc.z, acc.w);
    uint2 uo;
    uo.x = *reinterpret_cast<unsigned*>(&p0);
    uo.y = *reinterpret_cast<unsigned*>(&p1);
    ((uint2*)(g_a1h + (size_t)n * HID))[lane] = uo;
}

// ---------------- pass2 fused with pooling -----------------------------------
// agg2[n] = sum coef*relu_a1[src] + relu_a1[n]*dn^2; directly reduced into
// g_pool[batch[n]] via red.global.add.v4.f32 (no h2 array, no pool kernel).
__global__ void __launch_bounds__(256) k_pass2(const int* __restrict__ batch) {
    int n = blockIdx.x * 8 + (threadIdx.x >> 5);
    if (n >= N_NODES) return;
    int lane = threadIdx.x & 31;

    int r0 = __ldg(&g_rowptr[n]);
    int r1 = __ldg(&g_rowptr[n + 1]);
    float dn = __ldg(&g_dinv[n]);
    int g = __ldg(&batch[n]);

    uint2 u = __ldg(((const uint2*)(g_a1h + (size_t)n * HID)) + lane);
    float4 v = unpack_h4(u);
    float s = dn * dn;
    float4 acc = make_float4(v.x * s, v.y * s, v.z * s, v.w * s);

    int src_next = (r0 < r1) ? __ldg(&g_csrsrc[r0]) : 0;
    for (int j = r0; j < r1; j++) {
        int src = src_next;
        if (j + 1 < r1) src_next = __ldg(&g_csrsrc[j + 1]);
        float c = __ldg(&g_dinv[src]) * dn;
        uint2 us = __ldg(((const uint2*)(g_a1h + (size_t)src * HID)) + lane);
        float4 vs = unpack_h4(us);
        acc.x += vs.x * c; acc.y += vs.y * c;
        acc.z += vs.z * c; acc.w += vs.w * c;
    }

    float* pp = g_pool + (size_t)g * HID + lane * 4;
    asm volatile("red.global.add.v4.f32 [%0], {%1,%2,%3,%4};"
                 :: "l"(pp), "f"(acc.x), "f"(acc.y), "f"(acc.z), "f"(acc.w)
                 : "memory");
}

// ---------------- Wc = W2 @ Wfc ; Bc = b2 @ Wfc + bfc -----------------------
__global__ void k_wc(const float* __restrict__ W2, const float* __restrict__ Wfc,
                     const float* __restrict__ b2, const float* __restrict__ bfc) {
    int i = blockIdx.x;
    int j = threadIdx.x;
    float acc = 0.f;
    for (int k = 0; k < HID; k++) acc += W2[i * HID + k] * Wfc[k * HID + j];
    g_wc[i * HID + j] = acc;
    if (i == 0) {
        float a = bfc[j];
        for (int k = 0; k < HID; k++) a += b2[k] * Wfc[k * HID + j];
        g_bc[j] = a;
    }
}

// ---------------- final: out = (pool/cnt) @ Wc + Bc -------------------------
__global__ void k_out(float* __restrict__ out) {
    __shared__ float p[HID];
    int g = blockIdx.x;
    int c = threadIdx.x;
    float cnt = fmaxf(g_cnt[g], 1.f);
    p[c] = g_pool[g * HID + c] / cnt;
    __syncthreads();
    float acc = g_bc[c];
#pragma unroll 8
    for (int k = 0; k < HID; k++) acc += p[k] * g_wc[k * HID + c];
    out[g * HID + c] = acc;
}

// ---------------- launch ----------------------------------------------------
extern "C" void kernel_launch(void* const* d_in, const int* in_sizes, int n_in,
                              void* d_out, int out_size) {
    const int*   x     = (const int*)d_in[0];
    const int*   ei    = (const int*)d_in[1];
    const int*   batch = (const int*)d_in[3];
    const float* aemb  = (const float*)d_in[4];
    const float* W1    = (const float*)d_in[6];
    const float* b1    = (const float*)d_in[7];
    const float* W2    = (const float*)d_in[8];
    const float* b2    = (const float*)d_in[9];
    const float* Wfc   = (const float*)d_in[10];
    const float* bfc   = (const float*)d_in[11];
    float* out = (float*)d_out;

    k_init<<<2048, 256>>>();
    k_deg<<<2048, 256>>>(ei, batch);
    k_scan1<<<NSB, 256>>>();
    k_scan2<<<1, 512>>>();
    k_scan3<<<(N_NODES + 255) / 256, 256>>>();
    k_scatter<<<(N_EDGES + 255) / 256, 256>>>(ei);
    k_embed<<<592, 256>>>(x, aemb, W1);
    k_pass1<<<(N_NODES + 7) / 8, 256>>>(b1);
    k_pass2<<<(N_NODES + 7) / 8, 256>>>(batch);
    k_wc<<<HID, HID>>>(W2, Wfc, b2, bfc);
    k_out<<<N_GRAPHS, HID>>>(out);
}

// round 6
// speedup vs baseline: 2.0752x; 1.0755x over previous
#include <cuda_runtime.h>
#include <cuda_fp16.h>
#include <cstdint>

#define N_NODES 300000
#define N_EDGES 600000
#define N_GRAPHS 12000
#define HID 128
#define F_ATOM 9
#define V_ATOM 119
#define D_ATOM 9
#define EMB_SZ (F_ATOM * V_ATOM * D_ATOM)   // 9639 floats = 38556 B

#define SCAN_E 1024
#define NSB ((N_NODES + SCAN_E - 1) / SCAN_E)   // 293

// ---------------- scratch (device globals; no allocations allowed) ----------
__device__ __half g_h1h[(size_t)N_NODES * HID];   // h1 (fp16)
__device__ __half g_a1h[(size_t)N_NODES * HID];   // relu(agg1) (fp16)
__device__ int    g_deg[N_NODES];
__device__ float  g_dinv[N_NODES];
__device__ int    g_rowptr[N_NODES + 1];
__device__ int    g_fill[N_NODES];
__device__ int    g_csrsrc[N_EDGES];
__device__ int    g_bsum[NSB];
__device__ float  g_cnt[N_GRAPHS];
__device__ float  g_pool[N_GRAPHS * HID];
__device__ float  g_wc[HID * HID];
__device__ float  g_bc[HID];

// ---------------- init: deg=0, cnt=0, pool=0 --------------------------------
__global__ void k_init() {
    int i = blockIdx.x * blockDim.x + threadIdx.x;
    int stride = gridDim.x * blockDim.x;
    for (int j = i; j < N_GRAPHS * HID; j += stride) g_pool[j] = 0.f;
    for (int j = i; j < N_GRAPHS; j += stride) g_cnt[j] = 0.f;
    for (int j = i; j < N_NODES; j += stride) g_deg[j] = 0;
}

// ---------------- degree + per-graph node counts ----------------------------
__global__ void k_deg(const int* __restrict__ ei, const int* __restrict__ batch) {
    int i = blockIdx.x * blockDim.x + threadIdx.x;
    int stride = gridDim.x * blockDim.x;
    for (int e = i; e < N_EDGES; e += stride)
        atomicAdd(&g_deg[ei[N_EDGES + e]], 1);
    for (int n = i; n < N_NODES; n += stride)
        atomicAdd(&g_cnt[batch[n]], 1.f);
}

// ---------------- scan part 1: per-1024-block local inclusive scan ----------
__global__ void k_scan1() {
    __shared__ int s[256];
    int t = threadIdx.x;
    int base = blockIdx.x * SCAN_E + t * 4;
    int v[4];
#pragma unroll
    for (int k = 0; k < 4; k++) v[k] = (base + k < N_NODES) ? g_deg[base + k] : 0;
    v[1] += v[0]; v[2] += v[1]; v[3] += v[2];
    s[t] = v[3];
    __syncthreads();
    for (int off = 1; off < 256; off <<= 1) {
        int add = (t >= off) ? s[t - off] : 0;
        __syncthreads();
        s[t] += add;
        __syncthreads();
    }
    int pre = (t > 0) ? s[t - 1] : 0;
#pragma unroll
    for (int k = 0; k < 4; k++)
        if (base + k < N_NODES) g_rowptr[base + k + 1] = v[k] + pre;
    if (t == 255) g_bsum[blockIdx.x] = s[255];
}

// ---------------- scan parts 2+3 fused: every block re-scans the 293 bsums --
__global__ void __launch_bounds__(512) k_scan23() {
    __shared__ int s[512];
    int t = threadIdx.x;
    s[t] = (t < NSB) ? g_bsum[t] : 0;
    __syncthreads();
    for (int off = 1; off < 512; off <<= 1) {
        int v = (t >= off) ? s[t - off] : 0;
        __syncthreads();
        s[t] += v;
        __syncthreads();
    }
    int i = blockIdx.x * 512 + t;
    if (i >= N_NODES) return;
    int blk = i / SCAN_E;
    int add = (blk > 0) ? s[blk - 1] : 0;
    int incl = g_rowptr[i + 1] + add;
    g_rowptr[i + 1] = incl;
    int d = g_deg[i];
    g_fill[i] = incl - d;                        // exclusive start
    g_dinv[i] = rsqrtf((float)d + 1.0f);         // deg incl self-loop
    if (i == 0) g_rowptr[0] = 0;
}

// ---------------- scatter edges into CSR ------------------------------------
__global__ void k_scatter(const int* __restrict__ ei) {
    int e = blockIdx.x * blockDim.x + threadIdx.x;
    if (e >= N_EDGES) return;
    int src = ei[e];
    int dst = ei[N_EDGES + e];
    int pos = atomicAdd(&g_fill[dst], 1);
    g_csrsrc[pos] = src;
}

// ---------------- embed + h1 = h0@W1 (fp16 out) ------------------------------
__global__ void __launch_bounds__(256) k_embed(const int* __restrict__ x,
                                               const float* __restrict__ emb,
                                               const float* __restrict__ W1) {
    __shared__ float s_emb[EMB_SZ];
    __shared__ float s_h0[8][16];
    int tid = threadIdx.x;
    for (int i = tid; i < EMB_SZ; i += 256) s_emb[i] = emb[i];

    int warp = tid >> 5, lane = tid & 31;
    float4 w[D_ATOM];
    const float4* W1v = (const float4*)W1;
#pragma unroll
    for (int d = 0; d < D_ATOM; d++) w[d] = W1v[d * (HID / 4) + lane];
    __syncthreads();

    int gwarp = blockIdx.x * 8 + warp;
    const int NW = 592 * 8;
    for (int n = gwarp; n < N_NODES; n += NW) {
        int xv = 0;
        if (lane < F_ATOM) xv = __ldg(&x[n * F_ATOM + lane]);
        int xf[F_ATOM];
#pragma unroll
        for (int f = 0; f < F_ATOM; f++) xf[f] = __shfl_sync(0xffffffffu, xv, f);

        if (lane < D_ATOM) {
            float h = 0.f;
#pragma unroll
            for (int f = 0; f < F_ATOM; f++)
                h += s_emb[(f * V_ATOM + xf[f]) * D_ATOM + lane];
            s_h0[warp][lane] = h;
        }
        __syncwarp();
        float4 acc = make_float4(0.f, 0.f, 0.f, 0.f);
#pragma unroll
        for (int d = 0; d < D_ATOM; d++) {
            float h = s_h0[warp][d];
            acc.x += h * w[d].x; acc.y += h * w[d].y;
            acc.z += h * w[d].z; acc.w += h * w[d].w;
        }
        __syncwarp();

        __half2 p0 = __floats2half2_rn(acc.x, acc.y);
        __half2 p1 = __floats2half2_rn(acc.z, acc.w);
        uint2 u;
        u.x = *reinterpret_cast<unsigned*>(&p0);
        u.y = *reinterpret_cast<unsigned*>(&p1);
        ((uint2*)(g_h1h + (size_t)n * HID))[lane] = u;   // normal policy: stay L2-resident
    }
}

// ---------------- helpers ----------------------------------------------------
__device__ __forceinline__ float4 unpack_h4(uint2 u) {
    __half2 a = *reinterpret_cast<__half2*>(&u.x);
    __half2 b = *reinterpret_cast<__half2*>(&u.y);
    float2 fa = __half22float2(a), fb = __half22float2(b);
    return make_float4(fa.x, fa.y, fb.x, fb.y);
}

__device__ __forceinline__ void st_cs_v2(uint2* p, uint2 v) {
    asm volatile("st.global.cs.v2.u32 [%0], {%1,%2};"
                 :: "l"(p), "r"(v.x), "r"(v.y) : "memory");
}

// ---------------- pass1: relu(agg1) = relu(Â h1 + b1) -> g_a1h ---------------
// Output stored with evict-first (.cs) so h1 stays L2-resident for the gathers.
__global__ void __launch_bounds__(256) k_pass1(const float* __restrict__ b1) {
    int n = blockIdx.x * 8 + (threadIdx.x >> 5);
    if (n >= N_NODES) return;
    int lane = threadIdx.x & 31;

    int r0 = __ldg(&g_rowptr[n]);
    int r1 = __ldg(&g_rowptr[n + 1]);
    float dn = __ldg(&g_dinv[n]);

    uint2 u = __ldg(((const uint2*)(g_h1h + (size_t)n * HID)) + lane);
    float4 v = unpack_h4(u);
    float s = dn * dn;
    float4 bb = __ldg(((const float4*)b1) + lane);
    float4 acc = make_float4(v.x * s + bb.x, v.y * s + bb.y,
                             v.z * s + bb.z, v.w * s + bb.w);

    int src_next = (r0 < r1) ? __ldg(&g_csrsrc[r0]) : 0;
    for (int j = r0; j < r1; j++) {
        int src = src_next;
        if (j + 1 < r1) src_next = __ldg(&g_csrsrc[j + 1]);
        float c = __ldg(&g_dinv[src]) * dn;
        uint2 us = __ldg(((const uint2*)(g_h1h + (size_t)src * HID)) + lane);
        float4 vs = unpack_h4(us);
        acc.x += vs.x * c; acc.y += vs.y * c;
        acc.z += vs.z * c; acc.w += vs.w * c;
    }

    acc.x = fmaxf(acc.x, 0.f); acc.y = fmaxf(acc.y, 0.f);
    acc.z = fmaxf(acc.z, 0.f); acc.w = fmaxf(acc.w, 0.f);
    __half2 p0 = __floats2half2_rn(acc.x, acc.y);
    __half2 p1 = __floats2half2_rn(acc.z, acc.w);
    uint2 uo;
    uo.x = *reinterpret_cast<unsigned*>(&p0);
    uo.y = *reinterpret_cast<unsigned*>(&p1);
    st_cs_v2(((uint2*)(g_a1h + (size_t)n * HID)) + lane, uo);
}

// ---------------- pass2 fused with pooling -----------------------------------
__global__ void __launch_bounds__(256) k_pass2(const int* __restrict__ batch) {
    int n = blockIdx.x * 8 + (threadIdx.x >> 5);
    if (n >= N_NODES) return;
    int lane = threadIdx.x & 31;

    int r0 = __ldg(&g_rowptr[n]);
    int r1 = __ldg(&g_rowptr[n + 1]);
    float dn = __ldg(&g_dinv[n]);
    int g = __ldg(&batch[n]);

    uint2 u = __ldg(((const uint2*)(g_a1h + (size_t)n * HID)) + lane);
    float4 v = unpack_h4(u);
    float s = dn * dn;
    float4 acc = make_float4(v.x * s, v.y * s, v.z * s, v.w * s);

    int src_next = (r0 < r1) ? __ldg(&g_csrsrc[r0]) : 0;
    for (int j = r0; j < r1; j++) {
        int src = src_next;
        if (j + 1 < r1) src_next = __ldg(&g_csrsrc[j + 1]);
        float c = __ldg(&g_dinv[src]) * dn;
        uint2 us = __ldg(((const uint2*)(g_a1h + (size_t)src * HID)) + lane);
        float4 vs = unpack_h4(us);
        acc.x += vs.x * c; acc.y += vs.y * c;
        acc.z += vs.z * c; acc.w += vs.w * c;
    }

    float* pp = g_pool + (size_t)g * HID + lane * 4;
    asm volatile("red.global.add.v4.f32 [%0], {%1,%2,%3,%4};"
                 :: "l"(pp), "f"(acc.x), "f"(acc.y), "f"(acc.z), "f"(acc.w)
                 : "memory");
}

// ---------------- Wc = W2 @ Wfc ; Bc = b2 @ Wfc + bfc -----------------------
__global__ void k_wc(const float* __restrict__ W2, const float* __restrict__ Wfc,
                     const float* __restrict__ b2, const float* __restrict__ bfc) {
    int i = blockIdx.x;
    int j = threadIdx.x;
    float acc = 0.f;
    for (int k = 0; k < HID; k++) acc += W2[i * HID + k] * Wfc[k * HID + j];
    g_wc[i * HID + j] = acc;
    if (i == 0) {
        float a = bfc[j];
        for (int k = 0; k < HID; k++) a += b2[k] * Wfc[k * HID + j];
        g_bc[j] = a;
    }
}

// ---------------- final: out = (pool/cnt) @ Wc + Bc -------------------------
__global__ void k_out(float* __restrict__ out) {
    __shared__ float p[HID];
    int g = blockIdx.x;
    int c = threadIdx.x;
    float cnt = fmaxf(g_cnt[g], 1.f);
    p[c] = g_pool[g * HID + c] / cnt;
    __syncthreads();
    float acc = g_bc[c];
#pragma unroll 8
    for (int k = 0; k < HID; k++) acc += p[k] * g_wc[k * HID + c];
    out[g * HID + c] = acc;
}

// ---------------- launch: fork-join two-stream graph -------------------------
extern "C" void kernel_launch(void* const* d_in, const int* in_sizes, int n_in,
                              void* d_out, int out_size) {
    const int*   x     = (const int*)d_in[0];
    const int*   ei    = (const int*)d_in[1];
    const int*   batch = (const int*)d_in[3];
    const float* aemb  = (const float*)d_in[4];
    const float* W1    = (const float*)d_in[6];
    const float* b1    = (const float*)d_in[7];
    const float* W2    = (const float*)d_in[8];
    const float* b2    = (const float*)d_in[9];
    const float* Wfc   = (const float*)d_in[10];
    const float* bfc   = (const float*)d_in[11];
    float* out = (float*)d_out;

    static cudaStream_t sA = nullptr, sB = nullptr;
    static cudaEvent_t eF = nullptr, eA = nullptr, eB = nullptr;
    if (sA == nullptr) {
        cudaStreamCreateWithFlags(&sA, cudaStreamNonBlocking);
        cudaStreamCreateWithFlags(&sB, cudaStreamNonBlocking);
        cudaEventCreateWithFlags(&eF, cudaEventDisableTiming);
        cudaEventCreateWithFlags(&eA, cudaEventDisableTiming);
        cudaEventCreateWithFlags(&eB, cudaEventDisableTiming);
    }

    // fork from the (captured) base stream
    cudaEventRecord(eF, 0);
    cudaStreamWaitEvent(sA, eF, 0);
    cudaStreamWaitEvent(sB, eF, 0);

    // stream A: embedding layer + weight precompute (independent of graph structure)
    k_embed<<<592, 256, 0, sA>>>(x, aemb, W1);
    k_wc<<<HID, HID, 0, sA>>>(W2, Wfc, b2, bfc);

    // stream B: CSR build chain
    k_init<<<2048, 256, 0, sB>>>();
    k_deg<<<2048, 256, 0, sB>>>(ei, batch);
    k_scan1<<<NSB, 256, 0, sB>>>();
    k_scan23<<<(N_NODES + 511) / 512, 512, 0, sB>>>();
    k_scatter<<<(N_EDGES + 255) / 256, 256, 0, sB>>>(ei);

    // join back to base stream
    cudaEventRecord(eA, sA);
    cudaEventRecord(eB, sB);
    cudaStreamWaitEvent(0, eA, 0);
    cudaStreamWaitEvent(0, eB, 0);

    k_pass1<<<(N_NODES + 7) / 8, 256>>>(b1);
    k_pass2<<<(N_NODES + 7) / 8, 256>>>(batch);
    k_out<<<N_GRAPHS, HID>>>(out);
}